// round 10
// baseline (speedup 1.0000x reference)
#include <cuda_runtime.h>
#include <cuda_fp16.h>
#include <cstdint>

// smem: U ring 3 x 32KB, A ring 3 x 16KB, pvS 64KB, red
#define SM_U(s)   ((s) * 32768)              // [n=256][k=64] f16, swizzled
#define SM_A(s)   (98304 + (s) * 16384)      // A chunk staged, [ks][rb] fragment order
#define SM_PV     147456                     // prev [h=64][n=256] f32
#define SM_RED    212992                     // 32 f32
#define SM_TOTAL  213120

// W in m16n8k16 A-fragment order, chunk layout [ks][rb]: offset = ((ks*8+rb)*32+lane)*8+e
__device__ __align__(16) __half g_wA[983040];

__device__ __forceinline__ uint32_t sh_addr(const void* p) {
    return (uint32_t)__cvta_generic_to_shared(p);
}

__device__ __forceinline__ void mma16816(float* c, const uint4& a,
                                         uint32_t bq0, uint32_t bq1) {
    asm volatile(
        "mma.sync.aligned.m16n8k16.row.col.f32.f16.f16.f32 "
        "{%0,%1,%2,%3}, {%4,%5,%6,%7}, {%8,%9}, {%0,%1,%2,%3};"
        : "+f"(c[0]), "+f"(c[1]), "+f"(c[2]), "+f"(c[3])
        : "r"(a.x), "r"(a.y), "r"(a.z), "r"(a.w), "r"(bq0), "r"(bq1));
}

__device__ __forceinline__ void mma16808(float* c, uint32_t a0, uint32_t a1,
                                         uint32_t bq0) {
    asm volatile(
        "mma.sync.aligned.m16n8k8.row.col.f32.f16.f16.f32 "
        "{%0,%1,%2,%3}, {%4,%5}, {%6}, {%0,%1,%2,%3};"
        : "+f"(c[0]), "+f"(c[1]), "+f"(c[2]), "+f"(c[3])
        : "r"(a0), "r"(a1), "r"(bq0));
}

#define LDMX4(r0, r1, r2, r3, ad) \
    asm volatile("ldmatrix.sync.aligned.m8n8.x4.shared.b16 {%0,%1,%2,%3}, [%4];" \
        : "=r"(r0), "=r"(r1), "=r"(r2), "=r"(r3) : "r"(ad))

#define CPA16(dst, src) \
    asm volatile("cp.async.cg.shared.global [%0], [%1], 16;" :: "r"(dst), "l"(src))

// w[o][k][m] f32 (k < H real) -> g_wA fragment order ([ks][rb] within chunk), f16
__global__ void prep_w(const float* __restrict__ w, int H, int gBase) {
    int idx = blockIdx.x * blockDim.x + threadIdx.x;   // < 40*8192
    if (idx >= 40 * 8192) return;
    int e    = idx & 7;
    int lane = (idx >> 3) & 31;
    int ks   = (idx >> 8) & 3;
    int rb   = (idx >> 10) & 7;
    int m    = idx >> 13;
    int r = rb * 16 + (lane >> 2) + ((e >> 1) & 1) * 8;
    int k = ks * 16 + (lane & 3) * 2 + (e & 1) + ((e >> 2) & 1) * 8;
    float v = (k < H) ? w[r * (H * 40) + k * 40 + m] : 0.f;
    int dst = ((ks * 8 + rb) * 32 + lane) * 8 + e;     // [ks][rb] layout
    g_wA[(size_t)(gBase + m) * 8192 + dst] = __float2half(v);
}

__global__ void __launch_bounds__(512, 1) cin_mma(
    const float* __restrict__ x,
    const float* __restrict__ b0, const float* __restrict__ b1,
    const float* __restrict__ b2,
    const float* __restrict__ wl, float* __restrict__ out)
{
    extern __shared__ char smp[];
    float* pvS = (float*)(smp + SM_PV);
    float* red = (float*)(smp + SM_RED);
    int t = threadIdx.x, w = t >> 5, l = t & 31;
    int bb = blockIdx.x * 16;

    // ---- gen mapping: thread covers column gn, k-range [gh, gh+32) ----
    int gn = t & 255;
    int gh = (t >> 8) * 32;
    const float* xcolg = x + (size_t)(bb + (gn >> 4)) * 640 + (gn & 15);

    float pv[32];
    #pragma unroll
    for (int i = 0; i < 32; i++) {
        int h = gh + i;
        pv[i] = (h < 40) ? __ldg(xcolg + h * 16) : 0.f;   // layer-0 prev = x
    }

    uint32_t goff[4];
    #pragma unroll
    for (int j = 0; j < 4; j++)
        goff[j] = (uint32_t)(gn * 128 + ((((gh >> 3) + j) ^ (gn & 7)) * 16));

    // ---- MMA mapping: warp tile = 64 rows (rg) x 32 cols (cg); L2: 64x16 ----
    int rg = w >> 3, cg = w & 7;
    int kh = (l >> 3) & 1;
    int lrow = ((l >> 4) & 1) * 8 + (l & 7);

    float C[4][4][4];
    float accA0 = 0.f, accA1 = 0.f, accL2 = 0.f;
    const float* biasArr[3] = { b0, b1, b2 };

    for (int L = 0; L < 3; L++) {
        bool isL0 = (L == 0), isL2 = (L == 2);
        #pragma unroll
        for (int rbi = 0; rbi < 4; rbi++)
            #pragma unroll
            for (int nt = 0; nt < 4; nt++)
                #pragma unroll
                for (int i = 0; i < 4; i++) C[rbi][nt][i] = 0.f;
        int g0 = L * 40;
        int genJ = isL0 ? ((gh == 0) ? 4 : 1) : 4;    // L0: only k<40 rows

        for (int c = 0; c <= 40; c++) {
            if (c < 40) {
                // prefetch A(c) into ring slot c%3 (consumed next iteration)
                const char* src = (const char*)g_wA + (size_t)(g0 + c) * 16384;
                uint32_t dst = sh_addr(smp + SM_A(c % 3));
                if (isL0) {                    // ks 0..2 only: first 12KB
                    CPA16(dst + t * 16, src + t * 16);
                    if (t < 256) CPA16(dst + 8192 + t * 16, src + 8192 + t * 16);
                } else if (isL2) {             // live rows rb>=4: 2KB per ks block
                    uint32_t off = (uint32_t)((t >> 7) * 4096 + 2048 + (t & 127) * 16);
                    CPA16(dst + off, src + off);
                } else {                       // full 16KB
                    CPA16(dst + t * 16, src + t * 16);
                    CPA16(dst + 8192 + t * 16, src + 8192 + t * 16);
                }
                asm volatile("cp.async.commit_group;" ::: "memory");

                // generate U chunk c -> ring slot c%3
                float xv = __ldg(xcolg + c * 16);
                char* Ub = smp + SM_U(c % 3);
                #pragma unroll
                for (int j = 0; j < 4; j++) {
                    if (j >= genJ) break;
                    uint4 Hq; uint32_t* hh = (uint32_t*)&Hq;
                    #pragma unroll
                    for (int q = 0; q < 4; q++) {
                        __half2 h2 = __floats2half2_rn(xv * pv[j * 8 + q * 2],
                                                       xv * pv[j * 8 + q * 2 + 1]);
                        hh[q] = *(uint32_t*)&h2;
                    }
                    *(uint4*)(Ub + goff[j]) = Hq;
                }
                asm volatile("cp.async.wait_group 1;" ::: "memory");
            } else {
                asm volatile("cp.async.wait_group 0;" ::: "memory");
            }
            __syncthreads();   // all copies/gen of (c-1) visible; ring reuse safe (mod 3)

            if (c > 0) {
                int cc = c - 1;
                uint32_t ub = sh_addr(smp + SM_U(cc % 3));
                const char* Ab = smp + SM_A(cc % 3);
                if (isL0) {
                    // k0..31 via 2x k16, k32..39 via k8
                    #pragma unroll
                    for (int ks = 0; ks < 3; ks++) {
                        uint32_t br[4][2];
                        #pragma unroll
                        for (int ntp = 0; ntp < 2; ntp++) {
                            int n = cg * 32 + ntp * 16 + lrow;
                            uint32_t ad = ub + (uint32_t)(n * 128) +
                                          (uint32_t)((((ks * 2 + kh) ^ (n & 7)) * 16));
                            LDMX4(br[ntp * 2][0], br[ntp * 2][1],
                                  br[ntp * 2 + 1][0], br[ntp * 2 + 1][1], ad);
                        }
                        #pragma unroll
                        for (int rbi = 0; rbi < 4; rbi++) {
                            uint4 a = *(const uint4*)(Ab +
                                ((ks * 8 + rg * 4 + rbi) * 32 + l) * 16);
                            if (ks < 2) {
                                #pragma unroll
                                for (int nt = 0; nt < 4; nt++)
                                    mma16816(C[rbi][nt], a, br[nt][0], br[nt][1]);
                            } else {
                                #pragma unroll
                                for (int nt = 0; nt < 4; nt++)
                                    mma16808(C[rbi][nt], a.x, a.y, br[nt][0]);
                            }
                        }
                    }
                } else if (!isL2) {
                    #pragma unroll
                    for (int ks = 0; ks < 4; ks++) {
                        uint32_t br[4][2];
                        #pragma unroll
                        for (int ntp = 0; ntp < 2; ntp++) {
                            int n = cg * 32 + ntp * 16 + lrow;
                            uint32_t ad = ub + (uint32_t)(n * 128) +
                                          (uint32_t)((((ks * 2 + kh) ^ (n & 7)) * 16));
                            LDMX4(br[ntp * 2][0], br[ntp * 2][1],
                                  br[ntp * 2 + 1][0], br[ntp * 2 + 1][1], ad);
                        }
                        #pragma unroll
                        for (int rbi = 0; rbi < 4; rbi++) {
                            uint4 a = *(const uint4*)(Ab +
                                ((ks * 8 + rg * 4 + rbi) * 32 + l) * 16);
                            #pragma unroll
                            for (int nt = 0; nt < 4; nt++)
                                mma16816(C[rbi][nt], a, br[nt][0], br[nt][1]);
                        }
                    }
                } else {                        // rows 64..127, cols w*16..+16
                    #pragma unroll
                    for (int ks = 0; ks < 4; ks++) {
                        uint32_t br[2][2];
                        int n = w * 16 + lrow;
                        uint32_t ad = ub + (uint32_t)(n * 128) +
                                      (uint32_t)((((ks * 2 + kh) ^ (n & 7)) * 16));
                        LDMX4(br[0][0], br[0][1], br[1][0], br[1][1], ad);
                        #pragma unroll
                        for (int rbi = 0; rbi < 4; rbi++) {
                            uint4 a = *(const uint4*)(Ab +
                                ((ks * 8 + 4 + rbi) * 32 + l) * 16);
                            #pragma unroll
                            for (int nt = 0; nt < 2; nt++)
                                mma16816(C[rbi][nt], a, br[nt][0], br[nt][1]);
                        }
                    }
                }
            }
        }

        // ---- epilogue ----
        const float* bp = biasArr[L];
        if (!isL2) {
            #pragma unroll
            for (int rbi = 0; rbi < 4; rbi++) {
                int r0 = (rg * 4 + rbi) * 16 + (l >> 2);
                float bv0 = __ldg(bp + r0), bv1 = __ldg(bp + r0 + 8);
                float wl0 = 0.f, wl1 = 0.f;
                if (rg == 1) {
                    wl0 = __ldg(wl + L * 64 + r0 - 64);
                    wl1 = __ldg(wl + L * 64 + r0 - 56);
                }
                #pragma unroll
                for (int nt = 0; nt < 4; nt++) {
                    int n0 = cg * 32 + nt * 8 + (l & 3) * 2;
                    float v0 = fmaxf(C[rbi][nt][0] + bv0, 0.f);
                    float v1 = fmaxf(C[rbi][nt][1] + bv0, 0.f);
                    float v2 = fmaxf(C[rbi][nt][2] + bv1, 0.f);
                    float v3 = fmaxf(C[rbi][nt][3] + bv1, 0.f);
                    if (rg == 0) {              // prev half -> pvS
                        pvS[r0 * 256 + n0]           = v0;
                        pvS[r0 * 256 + n0 + 1]       = v1;
                        pvS[(r0 + 8) * 256 + n0]     = v2;
                        pvS[(r0 + 8) * 256 + n0 + 1] = v3;
                    } else {                    // direct half -> weighted acc
                        float a = wl0 * (v0 + v1) + wl1 * (v2 + v3);
                        if (nt < 2) accA0 += a; else accA1 += a;
                    }
                }
            }
            __syncthreads();                    // pvS writes visible
            #pragma unroll
            for (int i = 0; i < 32; i++) pv[i] = pvS[(gh + i) * 256 + gn];
        } else {
            #pragma unroll
            for (int rbi = 0; rbi < 4; rbi++) {
                int r0 = (4 + rbi) * 16 + (l >> 2);
                float bv0 = __ldg(bp + r0), bv1 = __ldg(bp + r0 + 8);
                float wl0 = __ldg(wl + 128 + r0 - 64);
                float wl1 = __ldg(wl + 128 + r0 - 56);
                #pragma unroll
                for (int nt = 0; nt < 2; nt++) {
                    float v0 = fmaxf(C[rbi][nt][0] + bv0, 0.f);
                    float v1 = fmaxf(C[rbi][nt][1] + bv0, 0.f);
                    float v2 = fmaxf(C[rbi][nt][2] + bv1, 0.f);
                    float v3 = fmaxf(C[rbi][nt][3] + bv1, 0.f);
                    accL2 += wl0 * (v0 + v1) + wl1 * (v2 + v3);
                }
            }
        }
    }

    // ---- deterministic reduction ----
    #pragma unroll
    for (int off = 16; off > 0; off >>= 1) {
        accA0 += __shfl_xor_sync(0xffffffffu, accA0, off);
        accA1 += __shfl_xor_sync(0xffffffffu, accA1, off);
        accL2 += __shfl_xor_sync(0xffffffffu, accL2, off);
    }
    __syncthreads();
    if (l == 0) {
        if (rg == 1) { red[2 * cg] = accA0; red[2 * cg + 1] = accA1; }
        red[16 + w] = accL2;
    }
    __syncthreads();
    if (t < 16) out[bb + t] = red[t] + red[16 + t];
}

extern "C" void kernel_launch(void* const* d_in, const int* in_sizes, int n_in,
                              void* d_out, int out_size) {
    const float* x  = (const float*)d_in[0];
    const float* w0 = (const float*)d_in[1];
    const float* b0 = (const float*)d_in[2];
    const float* w1 = (const float*)d_in[3];
    const float* b1 = (const float*)d_in[4];
    const float* w2 = (const float*)d_in[5];
    const float* b2 = (const float*)d_in[6];
    const float* wl = (const float*)d_in[7];
    float* out = (float*)d_out;

    cudaFuncSetAttribute(cin_mma, cudaFuncAttributeMaxDynamicSharedMemorySize,
                         SM_TOTAL);

    int np = 40 * 8192;
    prep_w<<<(np + 255) / 256, 256>>>(w0, 40, 0);
    prep_w<<<(np + 255) / 256, 256>>>(w1, 64, 40);
    prep_w<<<(np + 255) / 256, 256>>>(w2, 64, 80);

    cin_mma<<<128, 512, SM_TOTAL>>>(x, b0, b1, b2, wl, out);
}

// round 11
// speedup vs baseline: 1.0826x; 1.0826x over previous
#include <cuda_runtime.h>
#include <cuda_fp16.h>
#include <cstdint>

// smem: U ring 3 x 32KB, A ring 3 x 16KB, pvS 64KB, red
#define SM_U(s)   ((s) * 32768)              // [n=256][k=64] f16, swizzled
#define SM_A(s)   (98304 + (s) * 16384)      // A chunk staged linear
#define SM_PV     147456                     // prev [h=64][n=256] f32
#define SM_RED    212992                     // 32 f32
#define SM_TOTAL  213120

// W in m16n8k16 A-fragment order: [g=L*40+m][rb][ks][lane] x 8 halfs (16B)
__device__ __align__(16) __half g_wA[983040];

__device__ __forceinline__ uint32_t sh_addr(const void* p) {
    return (uint32_t)__cvta_generic_to_shared(p);
}

__device__ __forceinline__ void mma16816(float* c, const uint4& a,
                                         uint32_t bq0, uint32_t bq1) {
    asm volatile(
        "mma.sync.aligned.m16n8k16.row.col.f32.f16.f16.f32 "
        "{%0,%1,%2,%3}, {%4,%5,%6,%7}, {%8,%9}, {%0,%1,%2,%3};"
        : "+f"(c[0]), "+f"(c[1]), "+f"(c[2]), "+f"(c[3])
        : "r"(a.x), "r"(a.y), "r"(a.z), "r"(a.w), "r"(bq0), "r"(bq1));
}

#define LDMX4(r0, r1, r2, r3, ad) \
    asm volatile("ldmatrix.sync.aligned.m8n8.x4.shared.b16 {%0,%1,%2,%3}, [%4];" \
        : "=r"(r0), "=r"(r1), "=r"(r2), "=r"(r3) : "r"(ad))

#define CPA16(dst, src) \
    asm volatile("cp.async.cg.shared.global [%0], [%1], 16;" :: "r"(dst), "l"(src))

// w[o][k][m] f32 (k < H real) -> g_wA fragment order, f16
__global__ void prep_w(const float* __restrict__ w, int H, int gBase) {
    int idx = blockIdx.x * blockDim.x + threadIdx.x;   // < 40*8192
    if (idx >= 40 * 8192) return;
    int e    = idx & 7;
    int lane = (idx >> 3) & 31;
    int ks   = (idx >> 8) & 3;
    int rb   = (idx >> 10) & 7;
    int m    = idx >> 13;
    int r = rb * 16 + (lane >> 2) + ((e >> 1) & 1) * 8;
    int k = ks * 16 + (lane & 3) * 2 + (e & 1) + ((e >> 2) & 1) * 8;
    float v = (k < H) ? w[r * (H * 40) + k * 40 + m] : 0.f;
    g_wA[(size_t)(gBase + m) * 8192 + (idx & 8191)] = __float2half(v);
}

__global__ void __launch_bounds__(512, 1) cin_mma(
    const float* __restrict__ x,
    const float* __restrict__ b0, const float* __restrict__ b1,
    const float* __restrict__ b2,
    const float* __restrict__ wl, float* __restrict__ out)
{
    extern __shared__ char smp[];
    float* pvS = (float*)(smp + SM_PV);
    float* red = (float*)(smp + SM_RED);
    int t = threadIdx.x, w = t >> 5, l = t & 31;
    int bb = blockIdx.x * 16;

    // ---- gen mapping: thread covers column gn, k-range [gh, gh+32) ----
    int gn = t & 255;
    int gh = (t >> 8) * 32;
    const float* xcolg = x + (size_t)(bb + (gn >> 4)) * 640 + (gn & 15);

    float pv[32];
    #pragma unroll
    for (int i = 0; i < 32; i++) {
        int h = gh + i;
        pv[i] = (h < 40) ? __ldg(xcolg + h * 16) : 0.f;   // layer-0 prev = x
    }

    uint32_t goff[4];
    #pragma unroll
    for (int j = 0; j < 4; j++)
        goff[j] = (uint32_t)(gn * 128 + ((((gh >> 3) + j) ^ (gn & 7)) * 16));

    // ---- MMA mapping: warp tile = 64 rows (rg) x 32 cols (cg); L2: 64x16 ----
    int rg = w >> 3, cg = w & 7;
    int kh = (l >> 3) & 1;
    int lrow = ((l >> 4) & 1) * 8 + (l & 7);

    float C[4][4][4];
    float accA0 = 0.f, accA1 = 0.f, accL2 = 0.f;
    const float* biasArr[3] = { b0, b1, b2 };

    for (int L = 0; L < 3; L++) {
        bool isL0 = (L == 0), isL2 = (L == 2);
        #pragma unroll
        for (int rbi = 0; rbi < 4; rbi++)
            #pragma unroll
            for (int nt = 0; nt < 4; nt++)
                #pragma unroll
                for (int i = 0; i < 4; i++) C[rbi][nt][i] = 0.f;
        int g0 = L * 40;

        for (int c = 0; c <= 40; c++) {
            if (c < 40) {
                // prefetch A(c) into ring slot c%3 (consumed next iteration)
                const char* src = (const char*)g_wA + (size_t)(g0 + c) * 16384 + t * 16;
                uint32_t dst = sh_addr(smp + SM_A(c % 3)) + (uint32_t)(t * 16);
                CPA16(dst, src);
                CPA16(dst + 8192, src + 8192);
                asm volatile("cp.async.commit_group;" ::: "memory");

                // generate U chunk c -> ring slot c%3
                float xv = __ldg(xcolg + c * 16);
                char* Ub = smp + SM_U(c % 3);
                #pragma unroll
                for (int j = 0; j < 4; j++) {
                    uint4 Hq; uint32_t* hh = (uint32_t*)&Hq;
                    #pragma unroll
                    for (int q = 0; q < 4; q++) {
                        __half2 h2 = __floats2half2_rn(xv * pv[j * 8 + q * 2],
                                                       xv * pv[j * 8 + q * 2 + 1]);
                        hh[q] = *(uint32_t*)&h2;
                    }
                    *(uint4*)(Ub + goff[j]) = Hq;
                }
                // own A(c-1) group complete; A(c) stays in flight
                asm volatile("cp.async.wait_group 1;" ::: "memory");
            } else {
                asm volatile("cp.async.wait_group 0;" ::: "memory");
            }
            __syncthreads();   // all copies/gen of (c-1) visible; ring reuse safe (mod 3)

            if (c > 0) {
                int cc = c - 1;
                uint32_t ub = sh_addr(smp + SM_U(cc % 3));
                const char* Ab = smp + SM_A(cc % 3);
                if (!isL2) {
                    // L0: U rows k>=48 are exact zeros (pv=0 padding) -> skip ks=3
                    int ksN = isL0 ? 3 : 4;
                    #pragma unroll
                    for (int ks = 0; ks < 4; ks++) {
                        if (ks >= ksN) break;
                        uint32_t br[4][2];
                        #pragma unroll
                        for (int ntp = 0; ntp < 2; ntp++) {
                            int n = cg * 32 + ntp * 16 + lrow;
                            uint32_t ad = ub + (uint32_t)(n * 128) +
                                          (uint32_t)((((ks * 2 + kh) ^ (n & 7)) * 16));
                            LDMX4(br[ntp * 2][0], br[ntp * 2][1],
                                  br[ntp * 2 + 1][0], br[ntp * 2 + 1][1], ad);
                        }
                        #pragma unroll
                        for (int rbi = 0; rbi < 4; rbi++) {
                            uint4 a = *(const uint4*)(Ab +
                                (((rg * 4 + rbi) * 4 + ks) * 32 + l) * 16);
                            #pragma unroll
                            for (int nt = 0; nt < 4; nt++)
                                mma16816(C[rbi][nt], a, br[nt][0], br[nt][1]);
                        }
                    }
                } else {                        // rows 64..127, cols w*16..+16
                    #pragma unroll
                    for (int ks = 0; ks < 4; ks++) {
                        uint32_t br[2][2];
                        int n = w * 16 + lrow;
                        uint32_t ad = ub + (uint32_t)(n * 128) +
                                      (uint32_t)((((ks * 2 + kh) ^ (n & 7)) * 16));
                        LDMX4(br[0][0], br[0][1], br[1][0], br[1][1], ad);
                        #pragma unroll
                        for (int rbi = 0; rbi < 4; rbi++) {
                            uint4 a = *(const uint4*)(Ab +
                                (((4 + rbi) * 4 + ks) * 32 + l) * 16);
                            #pragma unroll
                            for (int nt = 0; nt < 2; nt++)
                                mma16816(C[rbi][nt], a, br[nt][0], br[nt][1]);
                        }
                    }
                }
            }
        }

        // ---- epilogue ----
        const float* bp = biasArr[L];
        if (!isL2) {
            #pragma unroll
            for (int rbi = 0; rbi < 4; rbi++) {
                int r0 = (rg * 4 + rbi) * 16 + (l >> 2);
                float bv0 = __ldg(bp + r0), bv1 = __ldg(bp + r0 + 8);
                float wl0 = 0.f, wl1 = 0.f;
                if (rg == 1) {
                    wl0 = __ldg(wl + L * 64 + r0 - 64);
                    wl1 = __ldg(wl + L * 64 + r0 - 56);
                }
                #pragma unroll
                for (int nt = 0; nt < 4; nt++) {
                    int n0 = cg * 32 + nt * 8 + (l & 3) * 2;
                    float v0 = fmaxf(C[rbi][nt][0] + bv0, 0.f);
                    float v1 = fmaxf(C[rbi][nt][1] + bv0, 0.f);
                    float v2 = fmaxf(C[rbi][nt][2] + bv1, 0.f);
                    float v3 = fmaxf(C[rbi][nt][3] + bv1, 0.f);
                    if (rg == 0) {              // prev half -> pvS
                        pvS[r0 * 256 + n0]           = v0;
                        pvS[r0 * 256 + n0 + 1]       = v1;
                        pvS[(r0 + 8) * 256 + n0]     = v2;
                        pvS[(r0 + 8) * 256 + n0 + 1] = v3;
                    } else {                    // direct half -> weighted acc
                        float a = wl0 * (v0 + v1) + wl1 * (v2 + v3);
                        if (nt < 2) accA0 += a; else accA1 += a;
                    }
                }
            }
            __syncthreads();                    // pvS writes visible
            #pragma unroll
            for (int i = 0; i < 32; i++) pv[i] = pvS[(gh + i) * 256 + gn];
        } else {
            #pragma unroll
            for (int rbi = 0; rbi < 4; rbi++) {
                int r0 = (4 + rbi) * 16 + (l >> 2);
                float bv0 = __ldg(bp + r0), bv1 = __ldg(bp + r0 + 8);
                float wl0 = __ldg(wl + 128 + r0 - 64);
                float wl1 = __ldg(wl + 128 + r0 - 56);
                #pragma unroll
                for (int nt = 0; nt < 2; nt++) {
                    float v0 = fmaxf(C[rbi][nt][0] + bv0, 0.f);
                    float v1 = fmaxf(C[rbi][nt][1] + bv0, 0.f);
                    float v2 = fmaxf(C[rbi][nt][2] + bv1, 0.f);
                    float v3 = fmaxf(C[rbi][nt][3] + bv1, 0.f);
                    accL2 += wl0 * (v0 + v1) + wl1 * (v2 + v3);
                }
            }
        }
    }

    // ---- deterministic reduction ----
    #pragma unroll
    for (int off = 16; off > 0; off >>= 1) {
        accA0 += __shfl_xor_sync(0xffffffffu, accA0, off);
        accA1 += __shfl_xor_sync(0xffffffffu, accA1, off);
        accL2 += __shfl_xor_sync(0xffffffffu, accL2, off);
    }
    __syncthreads();
    if (l == 0) {
        if (rg == 1) { red[2 * cg] = accA0; red[2 * cg + 1] = accA1; }
        red[16 + w] = accL2;
    }
    __syncthreads();
    if (t < 16) out[bb + t] = red[t] + red[16 + t];
}

extern "C" void kernel_launch(void* const* d_in, const int* in_sizes, int n_in,
                              void* d_out, int out_size) {
    const float* x  = (const float*)d_in[0];
    const float* w0 = (const float*)d_in[1];
    const float* b0 = (const float*)d_in[2];
    const float* w1 = (const float*)d_in[3];
    const float* b1 = (const float*)d_in[4];
    const float* w2 = (const float*)d_in[5];
    const float* b2 = (const float*)d_in[6];
    const float* wl = (const float*)d_in[7];
    float* out = (float*)d_out;

    cudaFuncSetAttribute(cin_mma, cudaFuncAttributeMaxDynamicSharedMemorySize,
                         SM_TOTAL);

    int np = 40 * 8192;
    prep_w<<<(np + 255) / 256, 256>>>(w0, 40, 0);
    prep_w<<<(np + 255) / 256, 256>>>(w1, 64, 40);
    prep_w<<<(np + 255) / 256, 256>>>(w2, 64, 80);

    cin_mma<<<128, 512, SM_TOTAL>>>(x, b0, b1, b2, wl, out);
}

// round 12
// speedup vs baseline: 1.1927x; 1.1017x over previous
#include <cuda_runtime.h>
#include <cuda_fp16.h>
#include <cstdint>

// smem: A double buffer 2x16KB, pvS f32 [64][260] (stride-260 -> conflict-free), red
#define SM_A(s)   ((s) * 16384)
#define SM_PV     32768
#define PVS       260
#define SM_RED    99328
#define SM_TOTAL  99456

// W in m16n8k16 A-fragment order: [g=L*40+m][rb][ks][lane] x 8 halfs (16B)
__device__ __align__(16) __half g_wA[983040];

__device__ __forceinline__ uint32_t sh_addr(const void* p) {
    return (uint32_t)__cvta_generic_to_shared(p);
}

__device__ __forceinline__ void mma16816(float* c, const uint4& a,
                                         uint32_t bq0, uint32_t bq1) {
    asm volatile(
        "mma.sync.aligned.m16n8k16.row.col.f32.f16.f16.f32 "
        "{%0,%1,%2,%3}, {%4,%5,%6,%7}, {%8,%9}, {%0,%1,%2,%3};"
        : "+f"(c[0]), "+f"(c[1]), "+f"(c[2]), "+f"(c[3])
        : "r"(a.x), "r"(a.y), "r"(a.z), "r"(a.w), "r"(bq0), "r"(bq1));
}

#define CPA16(dst, src) \
    asm volatile("cp.async.cg.shared.global [%0], [%1], 16;" :: "r"(dst), "l"(src))

// w[o][k][m] f32 (k < H real) -> g_wA fragment order, f16
__global__ void prep_w(const float* __restrict__ w, int H, int gBase) {
    int idx = blockIdx.x * blockDim.x + threadIdx.x;   // < 40*8192
    if (idx >= 40 * 8192) return;
    int e    = idx & 7;
    int lane = (idx >> 3) & 31;
    int ks   = (idx >> 8) & 3;
    int rb   = (idx >> 10) & 7;
    int m    = idx >> 13;
    int r = rb * 16 + (lane >> 2) + ((e >> 1) & 1) * 8;
    int k = ks * 16 + (lane & 3) * 2 + (e & 1) + ((e >> 2) & 1) * 8;
    float v = (k < H) ? w[r * (H * 40) + k * 40 + m] : 0.f;
    g_wA[(size_t)(gBase + m) * 8192 + (idx & 8191)] = __float2half(v);
}

__global__ void __launch_bounds__(512, 1) cin_mma(
    const float* __restrict__ x,
    const float* __restrict__ b0, const float* __restrict__ b1,
    const float* __restrict__ b2,
    const float* __restrict__ wl, float* __restrict__ out)
{
    extern __shared__ char smp[];
    float* pvS = (float*)(smp + SM_PV);
    float* red = (float*)(smp + SM_RED);
    int t = threadIdx.x, w = t >> 5, l = t & 31;
    int bb = blockIdx.x * 16;
    int rg = w >> 3, cg = w & 7;
    int lq = l >> 2, lr = l & 3;

    // x column pointers for this lane's fragment columns
    const float* xpA[4];    // layers 0/1: cols cg*32 + nt*8 + lq
    const float* xp2[2];    // layer 2:    cols w*16  + nt*8 + lq
    #pragma unroll
    for (int nt = 0; nt < 4; nt++) {
        int n = cg * 32 + nt * 8 + lq;
        xpA[nt] = x + (size_t)(bb + (n >> 4)) * 640 + (n & 15);
    }
    #pragma unroll
    for (int nt = 0; nt < 2; nt++) {
        int n = w * 16 + nt * 8 + lq;
        xp2[nt] = x + (size_t)(bb + (n >> 4)) * 640 + (n & 15);
    }

    // prev fragments in registers: pf[ks][nt][d] = half2{prev[k,n], prev[k+1,n]},
    // k = ks*16 + lr*2 + d*8.  Layer 0: prev = x (h<40 real).
    uint32_t pf[4][4][2];
    #pragma unroll
    for (int ks = 0; ks < 4; ks++)
        #pragma unroll
        for (int nt = 0; nt < 4; nt++)
            #pragma unroll
            for (int d = 0; d < 2; d++) {
                int h = ks * 16 + lr * 2 + d * 8;
                float v0 = (h < 40) ? __ldg(xpA[nt] + h * 16) : 0.f;
                float v1 = (h + 1 < 40) ? __ldg(xpA[nt] + (h + 1) * 16) : 0.f;
                __half2 hv = __floats2half2_rn(v0, v1);
                pf[ks][nt][d] = *(uint32_t*)&hv;
            }

    float C[4][4][4];
    float accA0 = 0.f, accA1 = 0.f, accL2 = 0.f;
    const float* biasArr[3] = { b0, b1, b2 };

    for (int L = 0; L < 3; L++) {
        bool isL0 = (L == 0), isL2 = (L == 2);
        int ksN = isL0 ? 3 : 4;     // L0: k>=48 rows are exact zeros
        #pragma unroll
        for (int rbi = 0; rbi < 4; rbi++)
            #pragma unroll
            for (int nt = 0; nt < 4; nt++)
                #pragma unroll
                for (int i = 0; i < 4; i++) C[rbi][nt][i] = 0.f;
        int g0 = L * 40;

        {   // prefetch A(chunk 0) -> slot 0
            const char* src = (const char*)g_wA + (size_t)g0 * 16384 + t * 16;
            uint32_t dst = sh_addr(smp + SM_A(0)) + (uint32_t)(t * 16);
            CPA16(dst, src);
            CPA16(dst + 8192, src + 8192);
            asm volatile("cp.async.commit_group;" ::: "memory");
        }

        for (int c = 0; c < 40; c++) {
            asm volatile("cp.async.wait_group 0;" ::: "memory");  // A(c) landed
            __syncthreads();                                       // slot reuse safe
            if (c + 1 < 40) {   // prefetch A(c+1) -> other slot, in flight this iter
                const char* src = (const char*)g_wA +
                                  (size_t)(g0 + c + 1) * 16384 + t * 16;
                uint32_t dst = sh_addr(smp + SM_A((c + 1) & 1)) + (uint32_t)(t * 16);
                CPA16(dst, src);
                CPA16(dst + 8192, src + 8192);
                asm volatile("cp.async.commit_group;" ::: "memory");
            }
            const char* Ab = smp + SM_A(c & 1);

            if (!isL2) {
                float xn[4];
                #pragma unroll
                for (int nt = 0; nt < 4; nt++) xn[nt] = __ldg(xpA[nt] + c * 16);
                #pragma unroll
                for (int ks = 0; ks < 4; ks++) {
                    if (ks >= ksN) break;
                    uint32_t b[4][2];
                    #pragma unroll
                    for (int nt = 0; nt < 4; nt++)
                        #pragma unroll
                        for (int d = 0; d < 2; d++) {
                            float2 p = __half22float2(*(__half2*)&pf[ks][nt][d]);
                            __half2 hv = __floats2half2_rn(p.x * xn[nt],
                                                           p.y * xn[nt]);
                            b[nt][d] = *(uint32_t*)&hv;
                        }
                    #pragma unroll
                    for (int rbi = 0; rbi < 4; rbi++) {
                        uint4 a = *(const uint4*)(Ab +
                            (((rg * 4 + rbi) * 4 + ks) * 32 + l) * 16);
                        #pragma unroll
                        for (int nt = 0; nt < 4; nt++)
                            mma16816(C[rbi][nt], a, b[nt][0], b[nt][1]);
                    }
                }
            } else {            // L2: rows 64..127, warp w covers cols w*16..+16
                float xn[2];
                #pragma unroll
                for (int nt = 0; nt < 2; nt++) xn[nt] = __ldg(xp2[nt] + c * 16);
                #pragma unroll
                for (int ks = 0; ks < 4; ks++) {
                    uint32_t b[2][2];
                    #pragma unroll
                    for (int nt = 0; nt < 2; nt++)
                        #pragma unroll
                        for (int d = 0; d < 2; d++) {
                            float2 p = __half22float2(*(__half2*)&pf[ks][nt][d]);
                            __half2 hv = __floats2half2_rn(p.x * xn[nt],
                                                           p.y * xn[nt]);
                            b[nt][d] = *(uint32_t*)&hv;
                        }
                    #pragma unroll
                    for (int rbi = 0; rbi < 4; rbi++) {
                        uint4 a = *(const uint4*)(Ab +
                            (((4 + rbi) * 4 + ks) * 32 + l) * 16);
                        #pragma unroll
                        for (int nt = 0; nt < 2; nt++)
                            mma16816(C[rbi][nt], a, b[nt][0], b[nt][1]);
                    }
                }
            }
        }

        // ---- epilogue ----
        const float* bp = biasArr[L];
        if (!isL2) {
            #pragma unroll
            for (int rbi = 0; rbi < 4; rbi++) {
                int r0 = (rg * 4 + rbi) * 16 + lq;
                float bv0 = __ldg(bp + r0), bv1 = __ldg(bp + r0 + 8);
                float wl0 = 0.f, wl1 = 0.f;
                if (rg == 1) {
                    wl0 = __ldg(wl + L * 64 + r0 - 64);
                    wl1 = __ldg(wl + L * 64 + r0 - 56);
                }
                #pragma unroll
                for (int nt = 0; nt < 4; nt++) {
                    int n0 = cg * 32 + nt * 8 + lr * 2;
                    float v0 = fmaxf(C[rbi][nt][0] + bv0, 0.f);
                    float v1 = fmaxf(C[rbi][nt][1] + bv0, 0.f);
                    float v2 = fmaxf(C[rbi][nt][2] + bv1, 0.f);
                    float v3 = fmaxf(C[rbi][nt][3] + bv1, 0.f);
                    if (rg == 0) {              // prev half -> pvS (stride 260)
                        pvS[r0 * PVS + n0]           = v0;
                        pvS[r0 * PVS + n0 + 1]       = v1;
                        pvS[(r0 + 8) * PVS + n0]     = v2;
                        pvS[(r0 + 8) * PVS + n0 + 1] = v3;
                    } else {                    // direct half -> weighted acc
                        float a = wl0 * (v0 + v1) + wl1 * (v2 + v3);
                        if (nt < 2) accA0 += a; else accA1 += a;
                    }
                }
            }
            __syncthreads();                    // pvS complete
            // reload prev fragments for layer L+1
            if (L == 0) {                       // next layer uses cols cg*32+...
                #pragma unroll
                for (int ks = 0; ks < 4; ks++)
                    #pragma unroll
                    for (int nt = 0; nt < 4; nt++)
                        #pragma unroll
                        for (int d = 0; d < 2; d++) {
                            int h = ks * 16 + lr * 2 + d * 8;
                            int n = cg * 32 + nt * 8 + lq;
                            __half2 hv = __floats2half2_rn(pvS[h * PVS + n],
                                                           pvS[(h + 1) * PVS + n]);
                            pf[ks][nt][d] = *(uint32_t*)&hv;
                        }
            } else {                            // next layer is L2: cols w*16+...
                #pragma unroll
                for (int ks = 0; ks < 4; ks++)
                    #pragma unroll
                    for (int nt = 0; nt < 2; nt++)
                        #pragma unroll
                        for (int d = 0; d < 2; d++) {
                            int h = ks * 16 + lr * 2 + d * 8;
                            int n = w * 16 + nt * 8 + lq;
                            __half2 hv = __floats2half2_rn(pvS[h * PVS + n],
                                                           pvS[(h + 1) * PVS + n]);
                            pf[ks][nt][d] = *(uint32_t*)&hv;
                        }
            }
        } else {
            #pragma unroll
            for (int rbi = 0; rbi < 4; rbi++) {
                int r0 = (4 + rbi) * 16 + lq;
                float bv0 = __ldg(bp + r0), bv1 = __ldg(bp + r0 + 8);
                float wl0 = __ldg(wl + 128 + r0 - 64);
                float wl1 = __ldg(wl + 128 + r0 - 56);
                #pragma unroll
                for (int nt = 0; nt < 2; nt++) {
                    float v0 = fmaxf(C[rbi][nt][0] + bv0, 0.f);
                    float v1 = fmaxf(C[rbi][nt][1] + bv0, 0.f);
                    float v2 = fmaxf(C[rbi][nt][2] + bv1, 0.f);
                    float v3 = fmaxf(C[rbi][nt][3] + bv1, 0.f);
                    accL2 += wl0 * (v0 + v1) + wl1 * (v2 + v3);
                }
            }
        }
    }

    // ---- deterministic reduction ----
    #pragma unroll
    for (int off = 16; off > 0; off >>= 1) {
        accA0 += __shfl_xor_sync(0xffffffffu, accA0, off);
        accA1 += __shfl_xor_sync(0xffffffffu, accA1, off);
        accL2 += __shfl_xor_sync(0xffffffffu, accL2, off);
    }
    __syncthreads();
    if (l == 0) {
        if (rg == 1) { red[2 * cg] = accA0; red[2 * cg + 1] = accA1; }
        red[16 + w] = accL2;
    }
    __syncthreads();
    if (t < 16) out[bb + t] = red[t] + red[16 + t];
}

extern "C" void kernel_launch(void* const* d_in, const int* in_sizes, int n_in,
                              void* d_out, int out_size) {
    const float* x  = (const float*)d_in[0];
    const float* w0 = (const float*)d_in[1];
    const float* b0 = (const float*)d_in[2];
    const float* w1 = (const float*)d_in[3];
    const float* b1 = (const float*)d_in[4];
    const float* w2 = (const float*)d_in[5];
    const float* b2 = (const float*)d_in[6];
    const float* wl = (const float*)d_in[7];
    float* out = (float*)d_out;

    cudaFuncSetAttribute(cin_mma, cudaFuncAttributeMaxDynamicSharedMemorySize,
                         SM_TOTAL);

    int np = 40 * 8192;
    prep_w<<<(np + 255) / 256, 256>>>(w0, 40, 0);
    prep_w<<<(np + 255) / 256, 256>>>(w1, 64, 40);
    prep_w<<<(np + 255) / 256, 256>>>(w2, 64, 80);

    cin_mma<<<128, 512, SM_TOTAL>>>(x, b0, b1, b2, wl, out);
}

// round 13
// speedup vs baseline: 1.2715x; 1.0661x over previous
#include <cuda_runtime.h>
#include <cuda_fp16.h>
#include <cstdint>

// smem: A double buffer 2x16KB, pvS f32 [64][260] (stride-260 -> conflict-free), red
#define SM_A(s)   ((s) * 16384)
#define SM_PV     32768
#define PVS       260
#define SM_RED    99328
#define SM_TOTAL  99456

// W in m16n8k16 A-fragment order: [g=L*40+m][rb][ks][lane] x 8 halfs (16B)
__device__ __align__(16) __half g_wA[983040];

__device__ __forceinline__ uint32_t sh_addr(const void* p) {
    return (uint32_t)__cvta_generic_to_shared(p);
}

__device__ __forceinline__ void mma16816(float* c, const uint4& a,
                                         uint32_t bq0, uint32_t bq1) {
    asm volatile(
        "mma.sync.aligned.m16n8k16.row.col.f32.f16.f16.f32 "
        "{%0,%1,%2,%3}, {%4,%5,%6,%7}, {%8,%9}, {%0,%1,%2,%3};"
        : "+f"(c[0]), "+f"(c[1]), "+f"(c[2]), "+f"(c[3])
        : "r"(a.x), "r"(a.y), "r"(a.z), "r"(a.w), "r"(bq0), "r"(bq1));
}

#define CPA16(dst, src) \
    asm volatile("cp.async.cg.shared.global [%0], [%1], 16;" :: "r"(dst), "l"(src))

__device__ __forceinline__ uint32_t hmul2u(uint32_t a, uint32_t b) {
    __half2 r = __hmul2(*(__half2*)&a, *(__half2*)&b);
    return *(uint32_t*)&r;
}

// w[o][k][m] f32 (k < H real) -> g_wA fragment order, f16
__global__ void prep_w(const float* __restrict__ w, int H, int gBase) {
    int idx = blockIdx.x * blockDim.x + threadIdx.x;   // < 40*8192
    if (idx >= 40 * 8192) return;
    int e    = idx & 7;
    int lane = (idx >> 3) & 31;
    int ks   = (idx >> 8) & 3;
    int rb   = (idx >> 10) & 7;
    int m    = idx >> 13;
    int r = rb * 16 + (lane >> 2) + ((e >> 1) & 1) * 8;
    int k = ks * 16 + (lane & 3) * 2 + (e & 1) + ((e >> 2) & 1) * 8;
    float v = (k < H) ? w[r * (H * 40) + k * 40 + m] : 0.f;
    g_wA[(size_t)(gBase + m) * 8192 + (idx & 8191)] = __float2half(v);
}

__global__ void __launch_bounds__(512, 1) cin_mma(
    const float* __restrict__ x,
    const float* __restrict__ b0, const float* __restrict__ b1,
    const float* __restrict__ b2,
    const float* __restrict__ wl, float* __restrict__ out)
{
    extern __shared__ char smp[];
    float* pvS = (float*)(smp + SM_PV);
    float* red = (float*)(smp + SM_RED);
    int t = threadIdx.x, w = t >> 5, l = t & 31;
    int bb = blockIdx.x * 16;
    int rg = w >> 3, cg = w & 7;
    int lq = l >> 2, lr = l & 3;

    // x column pointers for this lane's fragment columns
    const float* xpA[4];    // layers 0/1: cols cg*32 + nt*8 + lq
    const float* xp2[2];    // layer 2:    cols w*16  + nt*8 + lq
    #pragma unroll
    for (int nt = 0; nt < 4; nt++) {
        int n = cg * 32 + nt * 8 + lq;
        xpA[nt] = x + (size_t)(bb + (n >> 4)) * 640 + (n & 15);
    }
    #pragma unroll
    for (int nt = 0; nt < 2; nt++) {
        int n = w * 16 + nt * 8 + lq;
        xp2[nt] = x + (size_t)(bb + (n >> 4)) * 640 + (n & 15);
    }

    // prev fragments in registers: pf[ks][nt][d] = half2{prev[k,n], prev[k+1,n]},
    // k = ks*16 + lr*2 + d*8.  Layer 0: prev = x (h<40 real).
    uint32_t pf[4][4][2];
    #pragma unroll
    for (int ks = 0; ks < 4; ks++)
        #pragma unroll
        for (int nt = 0; nt < 4; nt++)
            #pragma unroll
            for (int d = 0; d < 2; d++) {
                int h = ks * 16 + lr * 2 + d * 8;
                float v0 = (h < 40) ? __ldg(xpA[nt] + h * 16) : 0.f;
                float v1 = (h + 1 < 40) ? __ldg(xpA[nt] + (h + 1) * 16) : 0.f;
                __half2 hv = __floats2half2_rn(v0, v1);
                pf[ks][nt][d] = *(uint32_t*)&hv;
            }

    float C[4][4][4];
    float accA0 = 0.f, accA1 = 0.f, accL2 = 0.f;
    const float* biasArr[3] = { b0, b1, b2 };

    for (int L = 0; L < 3; L++) {
        bool isL0 = (L == 0), isL2 = (L == 2);
        int ksN = isL0 ? 3 : 4;     // L0: k>=48 rows are exact zeros
        #pragma unroll
        for (int rbi = 0; rbi < 4; rbi++)
            #pragma unroll
            for (int nt = 0; nt < 4; nt++)
                #pragma unroll
                for (int i = 0; i < 4; i++) C[rbi][nt][i] = 0.f;
        int g0 = L * 40;

        {   // prefetch A(chunk 0) -> slot 0
            const char* src = (const char*)g_wA + (size_t)g0 * 16384 + t * 16;
            uint32_t dst = sh_addr(smp + SM_A(0)) + (uint32_t)(t * 16);
            CPA16(dst, src);
            CPA16(dst + 8192, src + 8192);
            asm volatile("cp.async.commit_group;" ::: "memory");
        }

        // x for chunk 0 (prefetched ahead each iteration thereafter)
        float xn[4];
        if (!isL2) {
            #pragma unroll
            for (int nt = 0; nt < 4; nt++) xn[nt] = __ldg(xpA[nt]);
        } else {
            #pragma unroll
            for (int nt = 0; nt < 2; nt++) xn[nt] = __ldg(xp2[nt]);
        }

        for (int c = 0; c < 40; c++) {
            asm volatile("cp.async.wait_group 0;" ::: "memory");  // A(c) landed
            __syncthreads();                                       // slot reuse safe
            if (c + 1 < 40) {   // prefetch A(c+1) -> other slot, in flight this iter
                const char* src = (const char*)g_wA +
                                  (size_t)(g0 + c + 1) * 16384 + t * 16;
                uint32_t dst = sh_addr(smp + SM_A((c + 1) & 1)) + (uint32_t)(t * 16);
                CPA16(dst, src);
                CPA16(dst + 8192, src + 8192);
                asm volatile("cp.async.commit_group;" ::: "memory");
            }
            const char* Ab = smp + SM_A(c & 1);

            if (!isL2) {
                // broadcast-convert this chunk's x, then prefetch next chunk's x
                uint32_t xh[4];
                #pragma unroll
                for (int nt = 0; nt < 4; nt++) {
                    __half2 h2 = __float2half2_rn(xn[nt]);
                    xh[nt] = *(uint32_t*)&h2;
                }
                if (c + 1 < 40) {
                    #pragma unroll
                    for (int nt = 0; nt < 4; nt++)
                        xn[nt] = __ldg(xpA[nt] + (c + 1) * 16);
                }
                #pragma unroll
                for (int ks = 0; ks < 4; ks++) {
                    if (ks >= ksN) break;
                    uint32_t b[4][2];
                    #pragma unroll
                    for (int nt = 0; nt < 4; nt++) {
                        b[nt][0] = hmul2u(pf[ks][nt][0], xh[nt]);
                        b[nt][1] = hmul2u(pf[ks][nt][1], xh[nt]);
                    }
                    #pragma unroll
                    for (int rbi = 0; rbi < 4; rbi++) {
                        uint4 a = *(const uint4*)(Ab +
                            (((rg * 4 + rbi) * 4 + ks) * 32 + l) * 16);
                        #pragma unroll
                        for (int nt = 0; nt < 4; nt++)
                            mma16816(C[rbi][nt], a, b[nt][0], b[nt][1]);
                    }
                }
            } else {            // L2: rows 64..127, warp w covers cols w*16..+16
                uint32_t xh[2];
                #pragma unroll
                for (int nt = 0; nt < 2; nt++) {
                    __half2 h2 = __float2half2_rn(xn[nt]);
                    xh[nt] = *(uint32_t*)&h2;
                }
                if (c + 1 < 40) {
                    #pragma unroll
                    for (int nt = 0; nt < 2; nt++)
                        xn[nt] = __ldg(xp2[nt] + (c + 1) * 16);
                }
                #pragma unroll
                for (int ks = 0; ks < 4; ks++) {
                    uint32_t b[2][2];
                    #pragma unroll
                    for (int nt = 0; nt < 2; nt++) {
                        b[nt][0] = hmul2u(pf[ks][nt][0], xh[nt]);
                        b[nt][1] = hmul2u(pf[ks][nt][1], xh[nt]);
                    }
                    #pragma unroll
                    for (int rbi = 0; rbi < 4; rbi++) {
                        uint4 a = *(const uint4*)(Ab +
                            (((4 + rbi) * 4 + ks) * 32 + l) * 16);
                        #pragma unroll
                        for (int nt = 0; nt < 2; nt++)
                            mma16816(C[rbi][nt], a, b[nt][0], b[nt][1]);
                    }
                }
            }
        }

        // ---- epilogue ----
        const float* bp = biasArr[L];
        if (!isL2) {
            #pragma unroll
            for (int rbi = 0; rbi < 4; rbi++) {
                int r0 = (rg * 4 + rbi) * 16 + lq;
                float bv0 = __ldg(bp + r0), bv1 = __ldg(bp + r0 + 8);
                float wl0 = 0.f, wl1 = 0.f;
                if (rg == 1) {
                    wl0 = __ldg(wl + L * 64 + r0 - 64);
                    wl1 = __ldg(wl + L * 64 + r0 - 56);
                }
                #pragma unroll
                for (int nt = 0; nt < 4; nt++) {
                    int n0 = cg * 32 + nt * 8 + lr * 2;
                    float v0 = fmaxf(C[rbi][nt][0] + bv0, 0.f);
                    float v1 = fmaxf(C[rbi][nt][1] + bv0, 0.f);
                    float v2 = fmaxf(C[rbi][nt][2] + bv1, 0.f);
                    float v3 = fmaxf(C[rbi][nt][3] + bv1, 0.f);
                    if (rg == 0) {              // prev half -> pvS (stride 260)
                        pvS[r0 * PVS + n0]           = v0;
                        pvS[r0 * PVS + n0 + 1]       = v1;
                        pvS[(r0 + 8) * PVS + n0]     = v2;
                        pvS[(r0 + 8) * PVS + n0 + 1] = v3;
                    } else {                    // direct half -> weighted acc
                        float a = wl0 * (v0 + v1) + wl1 * (v2 + v3);
                        if (nt < 2) accA0 += a; else accA1 += a;
                    }
                }
            }
            __syncthreads();                    // pvS complete
            // reload prev fragments for layer L+1
            if (L == 0) {                       // next layer uses cols cg*32+...
                #pragma unroll
                for (int ks = 0; ks < 4; ks++)
                    #pragma unroll
                    for (int nt = 0; nt < 4; nt++)
                        #pragma unroll
                        for (int d = 0; d < 2; d++) {
                            int h = ks * 16 + lr * 2 + d * 8;
                            int n = cg * 32 + nt * 8 + lq;
                            __half2 hv = __floats2half2_rn(pvS[h * PVS + n],
                                                           pvS[(h + 1) * PVS + n]);
                            pf[ks][nt][d] = *(uint32_t*)&hv;
                        }
            } else {                            // next layer is L2: cols w*16+...
                #pragma unroll
                for (int ks = 0; ks < 4; ks++)
                    #pragma unroll
                    for (int nt = 0; nt < 2; nt++)
                        #pragma unroll
                        for (int d = 0; d < 2; d++) {
                            int h = ks * 16 + lr * 2 + d * 8;
                            int n = w * 16 + nt * 8 + lq;
                            __half2 hv = __floats2half2_rn(pvS[h * PVS + n],
                                                           pvS[(h + 1) * PVS + n]);
                            pf[ks][nt][d] = *(uint32_t*)&hv;
                        }
            }
        } else {
            #pragma unroll
            for (int rbi = 0; rbi < 4; rbi++) {
                int r0 = (4 + rbi) * 16 + lq;
                float bv0 = __ldg(bp + r0), bv1 = __ldg(bp + r0 + 8);
                float wl0 = __ldg(wl + 128 + r0 - 64);
                float wl1 = __ldg(wl + 128 + r0 - 56);
                #pragma unroll
                for (int nt = 0; nt < 2; nt++) {
                    float v0 = fmaxf(C[rbi][nt][0] + bv0, 0.f);
                    float v1 = fmaxf(C[rbi][nt][1] + bv0, 0.f);
                    float v2 = fmaxf(C[rbi][nt][2] + bv1, 0.f);
                    float v3 = fmaxf(C[rbi][nt][3] + bv1, 0.f);
                    accL2 += wl0 * (v0 + v1) + wl1 * (v2 + v3);
                }
            }
        }
    }

    // ---- deterministic reduction ----
    #pragma unroll
    for (int off = 16; off > 0; off >>= 1) {
        accA0 += __shfl_xor_sync(0xffffffffu, accA0, off);
        accA1 += __shfl_xor_sync(0xffffffffu, accA1, off);
        accL2 += __shfl_xor_sync(0xffffffffu, accL2, off);
    }
    __syncthreads();
    if (l == 0) {
        if (rg == 1) { red[2 * cg] = accA0; red[2 * cg + 1] = accA1; }
        red[16 + w] = accL2;
    }
    __syncthreads();
    if (t < 16) out[bb + t] = red[t] + red[16 + t];
}

extern "C" void kernel_launch(void* const* d_in, const int* in_sizes, int n_in,
                              void* d_out, int out_size) {
    const float* x  = (const float*)d_in[0];
    const float* w0 = (const float*)d_in[1];
    const float* b0 = (const float*)d_in[2];
    const float* w1 = (const float*)d_in[3];
    const float* b1 = (const float*)d_in[4];
    const float* w2 = (const float*)d_in[5];
    const float* b2 = (const float*)d_in[6];
    const float* wl = (const float*)d_in[7];
    float* out = (float*)d_out;

    cudaFuncSetAttribute(cin_mma, cudaFuncAttributeMaxDynamicSharedMemorySize,
                         SM_TOTAL);

    int np = 40 * 8192;
    prep_w<<<(np + 255) / 256, 256>>>(w0, 40, 0);
    prep_w<<<(np + 255) / 256, 256>>>(w1, 64, 40);
    prep_w<<<(np + 255) / 256, 256>>>(w2, 64, 80);

    cin_mma<<<128, 512, SM_TOTAL>>>(x, b0, b1, b2, wl, out);
}

// round 14
// speedup vs baseline: 1.2977x; 1.0206x over previous
#include <cuda_runtime.h>
#include <cuda_fp16.h>
#include <cstdint>

// smem: A ring 4x16KB, pvS f32 [64][260] (stride-260 -> conflict-free), red
#define SM_A(s)   ((s) * 16384)
#define SM_PV     65536
#define PVS       260
#define SM_RED    132096
#define SM_TOTAL  132224

// W in m16n8k16 A-fragment order: [g=L*40+m][rb][ks][lane] x 8 halfs (16B)
__device__ __align__(16) __half g_wA[983040];

__device__ __forceinline__ uint32_t sh_addr(const void* p) {
    return (uint32_t)__cvta_generic_to_shared(p);
}

__device__ __forceinline__ void mma16816(float* c, const uint4& a,
                                         uint32_t bq0, uint32_t bq1) {
    asm volatile(
        "mma.sync.aligned.m16n8k16.row.col.f32.f16.f16.f32 "
        "{%0,%1,%2,%3}, {%4,%5,%6,%7}, {%8,%9}, {%0,%1,%2,%3};"
        : "+f"(c[0]), "+f"(c[1]), "+f"(c[2]), "+f"(c[3])
        : "r"(a.x), "r"(a.y), "r"(a.z), "r"(a.w), "r"(bq0), "r"(bq1));
}

#define CPA16(dst, src) \
    asm volatile("cp.async.cg.shared.global [%0], [%1], 16;" :: "r"(dst), "l"(src))

__device__ __forceinline__ uint32_t hmul2u(uint32_t a, uint32_t b) {
    __half2 r = __hmul2(*(__half2*)&a, *(__half2*)&b);
    return *(uint32_t*)&r;
}

// w[o][k][m] f32 (k < H real) -> g_wA fragment order, f16
__global__ void prep_w(const float* __restrict__ w, int H, int gBase) {
    int idx = blockIdx.x * blockDim.x + threadIdx.x;   // < 40*8192
    if (idx >= 40 * 8192) return;
    int e    = idx & 7;
    int lane = (idx >> 3) & 31;
    int ks   = (idx >> 8) & 3;
    int rb   = (idx >> 10) & 7;
    int m    = idx >> 13;
    int r = rb * 16 + (lane >> 2) + ((e >> 1) & 1) * 8;
    int k = ks * 16 + (lane & 3) * 2 + (e & 1) + ((e >> 2) & 1) * 8;
    float v = (k < H) ? w[r * (H * 40) + k * 40 + m] : 0.f;
    g_wA[(size_t)(gBase + m) * 8192 + (idx & 8191)] = __float2half(v);
}

__global__ void __launch_bounds__(512, 1) cin_mma(
    const float* __restrict__ x,
    const float* __restrict__ b0, const float* __restrict__ b1,
    const float* __restrict__ b2,
    const float* __restrict__ wl, float* __restrict__ out)
{
    extern __shared__ char smp[];
    float* pvS = (float*)(smp + SM_PV);
    float* red = (float*)(smp + SM_RED);
    int t = threadIdx.x, w = t >> 5, l = t & 31;
    int bb = blockIdx.x * 16;
    int rg = w >> 3, cg = w & 7;
    int lq = l >> 2, lr = l & 3;

    // x column pointers for this lane's fragment columns
    const float* xpA[4];    // layers 0/1: cols cg*32 + nt*8 + lq
    const float* xp2[2];    // layer 2:    cols w*16  + nt*8 + lq
    #pragma unroll
    for (int nt = 0; nt < 4; nt++) {
        int n = cg * 32 + nt * 8 + lq;
        xpA[nt] = x + (size_t)(bb + (n >> 4)) * 640 + (n & 15);
    }
    #pragma unroll
    for (int nt = 0; nt < 2; nt++) {
        int n = w * 16 + nt * 8 + lq;
        xp2[nt] = x + (size_t)(bb + (n >> 4)) * 640 + (n & 15);
    }

    // prev fragments in registers: pf[ks][nt][d] = half2{prev[k,n], prev[k+1,n]},
    // k = ks*16 + lr*2 + d*8.  Layer 0: prev = x (h<40 real).
    uint32_t pf[4][4][2];
    #pragma unroll
    for (int ks = 0; ks < 4; ks++)
        #pragma unroll
        for (int nt = 0; nt < 4; nt++)
            #pragma unroll
            for (int d = 0; d < 2; d++) {
                int h = ks * 16 + lr * 2 + d * 8;
                float v0 = (h < 40) ? __ldg(xpA[nt] + h * 16) : 0.f;
                float v1 = (h + 1 < 40) ? __ldg(xpA[nt] + (h + 1) * 16) : 0.f;
                __half2 hv = __floats2half2_rn(v0, v1);
                pf[ks][nt][d] = *(uint32_t*)&hv;
            }

    float C[4][4][4];
    float accA0 = 0.f, accA1 = 0.f, accL2 = 0.f;
    const float* biasArr[3] = { b0, b1, b2 };

    for (int L = 0; L < 3; L++) {
        bool isL0 = (L == 0), isL2 = (L == 2);
        int ksN = isL0 ? 3 : 4;     // L0: k>=48 rows are exact zeros
        #pragma unroll
        for (int rbi = 0; rbi < 4; rbi++)
            #pragma unroll
            for (int nt = 0; nt < 4; nt++)
                #pragma unroll
                for (int i = 0; i < 4; i++) C[rbi][nt][i] = 0.f;
        int g0 = L * 40;

        {   // prologue: prefetch chunks 0,1 -> slots 0,1 (one group)
            const char* s0 = (const char*)g_wA + (size_t)g0 * 16384 + t * 16;
            uint32_t d0 = sh_addr(smp + SM_A(0)) + (uint32_t)(t * 16);
            CPA16(d0, s0);
            CPA16(d0 + 8192, s0 + 8192);
            CPA16(d0 + 16384, s0 + 16384);
            CPA16(d0 + 24576, s0 + 24576);
            asm volatile("cp.async.commit_group;" ::: "memory");
        }

        // x for chunk 0 (prefetched ahead each chunk thereafter)
        float xn[4];
        if (!isL2) {
            #pragma unroll
            for (int nt = 0; nt < 4; nt++) xn[nt] = __ldg(xpA[nt]);
        } else {
            #pragma unroll
            for (int nt = 0; nt < 2; nt++) xn[nt] = __ldg(xp2[nt]);
        }

        for (int cp = 0; cp < 20; cp++) {
            int c0 = cp * 2;
            asm volatile("cp.async.wait_group 0;" ::: "memory");  // pair cp landed
            __syncthreads();                                       // ring reuse safe
            if (c0 + 2 < 40) {  // prefetch pair cp+1 -> slots (c0+2)&3,(c0+3)&3
                const char* s0 = (const char*)g_wA +
                                 (size_t)(g0 + c0 + 2) * 16384 + t * 16;
                uint32_t d0 = sh_addr(smp + SM_A((c0 + 2) & 3)) + (uint32_t)(t * 16);
                uint32_t d1 = sh_addr(smp + SM_A((c0 + 3) & 3)) + (uint32_t)(t * 16);
                CPA16(d0, s0);
                CPA16(d0 + 8192, s0 + 8192);
                CPA16(d1, s0 + 16384);
                CPA16(d1 + 8192, s0 + 24576);
            }
            asm volatile("cp.async.commit_group;" ::: "memory");

            #pragma unroll
            for (int sub = 0; sub < 2; sub++) {
                int c = c0 + sub;
                const char* Ab = smp + SM_A(c & 3);

                if (!isL2) {
                    uint32_t xh[4];
                    #pragma unroll
                    for (int nt = 0; nt < 4; nt++) {
                        __half2 h2 = __float2half2_rn(xn[nt]);
                        xh[nt] = *(uint32_t*)&h2;
                    }
                    if (c + 1 < 40) {
                        #pragma unroll
                        for (int nt = 0; nt < 4; nt++)
                            xn[nt] = __ldg(xpA[nt] + (c + 1) * 16);
                    }
                    #pragma unroll
                    for (int ks = 0; ks < 4; ks++) {
                        if (ks >= ksN) break;
                        uint32_t b[4][2];
                        #pragma unroll
                        for (int nt = 0; nt < 4; nt++) {
                            b[nt][0] = hmul2u(pf[ks][nt][0], xh[nt]);
                            b[nt][1] = hmul2u(pf[ks][nt][1], xh[nt]);
                        }
                        #pragma unroll
                        for (int rbi = 0; rbi < 4; rbi++) {
                            uint4 a = *(const uint4*)(Ab +
                                (((rg * 4 + rbi) * 4 + ks) * 32 + l) * 16);
                            #pragma unroll
                            for (int nt = 0; nt < 4; nt++)
                                mma16816(C[rbi][nt], a, b[nt][0], b[nt][1]);
                        }
                    }
                } else {        // L2: rows 64..127, warp w covers cols w*16..+16
                    uint32_t xh[2];
                    #pragma unroll
                    for (int nt = 0; nt < 2; nt++) {
                        __half2 h2 = __float2half2_rn(xn[nt]);
                        xh[nt] = *(uint32_t*)&h2;
                    }
                    if (c + 1 < 40) {
                        #pragma unroll
                        for (int nt = 0; nt < 2; nt++)
                            xn[nt] = __ldg(xp2[nt] + (c + 1) * 16);
                    }
                    #pragma unroll
                    for (int ks = 0; ks < 4; ks++) {
                        uint32_t b[2][2];
                        #pragma unroll
                        for (int nt = 0; nt < 2; nt++) {
                            b[nt][0] = hmul2u(pf[ks][nt][0], xh[nt]);
                            b[nt][1] = hmul2u(pf[ks][nt][1], xh[nt]);
                        }
                        #pragma unroll
                        for (int rbi = 0; rbi < 4; rbi++) {
                            uint4 a = *(const uint4*)(Ab +
                                (((4 + rbi) * 4 + ks) * 32 + l) * 16);
                            #pragma unroll
                            for (int nt = 0; nt < 2; nt++)
                                mma16816(C[rbi][nt], a, b[nt][0], b[nt][1]);
                        }
                    }
                }
            }
        }

        // ---- epilogue ----
        const float* bp = biasArr[L];
        if (!isL2) {
            #pragma unroll
            for (int rbi = 0; rbi < 4; rbi++) {
                int r0 = (rg * 4 + rbi) * 16 + lq;
                float bv0 = __ldg(bp + r0), bv1 = __ldg(bp + r0 + 8);
                float wl0 = 0.f, wl1 = 0.f;
                if (rg == 1) {
                    wl0 = __ldg(wl + L * 64 + r0 - 64);
                    wl1 = __ldg(wl + L * 64 + r0 - 56);
                }
                #pragma unroll
                for (int nt = 0; nt < 4; nt++) {
                    int n0 = cg * 32 + nt * 8 + lr * 2;
                    float v0 = fmaxf(C[rbi][nt][0] + bv0, 0.f);
                    float v1 = fmaxf(C[rbi][nt][1] + bv0, 0.f);
                    float v2 = fmaxf(C[rbi][nt][2] + bv1, 0.f);
                    float v3 = fmaxf(C[rbi][nt][3] + bv1, 0.f);
                    if (rg == 0) {              // prev half -> pvS (stride 260)
                        pvS[r0 * PVS + n0]           = v0;
                        pvS[r0 * PVS + n0 + 1]       = v1;
                        pvS[(r0 + 8) * PVS + n0]     = v2;
                        pvS[(r0 + 8) * PVS + n0 + 1] = v3;
                    } else {                    // direct half -> weighted acc
                        float a = wl0 * (v0 + v1) + wl1 * (v2 + v3);
                        if (nt < 2) accA0 += a; else accA1 += a;
                    }
                }
            }
            __syncthreads();                    // pvS complete
            // reload prev fragments for layer L+1
            if (L == 0) {                       // next layer uses cols cg*32+...
                #pragma unroll
                for (int ks = 0; ks < 4; ks++)
                    #pragma unroll
                    for (int nt = 0; nt < 4; nt++)
                        #pragma unroll
                        for (int d = 0; d < 2; d++) {
                            int h = ks * 16 + lr * 2 + d * 8;
                            int n = cg * 32 + nt * 8 + lq;
                            __half2 hv = __floats2half2_rn(pvS[h * PVS + n],
                                                           pvS[(h + 1) * PVS + n]);
                            pf[ks][nt][d] = *(uint32_t*)&hv;
                        }
            } else {                            // next layer is L2: cols w*16+...
                #pragma unroll
                for (int ks = 0; ks < 4; ks++)
                    #pragma unroll
                    for (int nt = 0; nt < 2; nt++)
                        #pragma unroll
                        for (int d = 0; d < 2; d++) {
                            int h = ks * 16 + lr * 2 + d * 8;
                            int n = w * 16 + nt * 8 + lq;
                            __half2 hv = __floats2half2_rn(pvS[h * PVS + n],
                                                           pvS[(h + 1) * PVS + n]);
                            pf[ks][nt][d] = *(uint32_t*)&hv;
                        }
            }
        } else {
            #pragma unroll
            for (int rbi = 0; rbi < 4; rbi++) {
                int r0 = (4 + rbi) * 16 + lq;
                float bv0 = __ldg(bp + r0), bv1 = __ldg(bp + r0 + 8);
                float wl0 = __ldg(wl + 128 + r0 - 64);
                float wl1 = __ldg(wl + 128 + r0 - 56);
                #pragma unroll
                for (int nt = 0; nt < 2; nt++) {
                    float v0 = fmaxf(C[rbi][nt][0] + bv0, 0.f);
                    float v1 = fmaxf(C[rbi][nt][1] + bv0, 0.f);
                    float v2 = fmaxf(C[rbi][nt][2] + bv1, 0.f);
                    float v3 = fmaxf(C[rbi][nt][3] + bv1, 0.f);
                    accL2 += wl0 * (v0 + v1) + wl1 * (v2 + v3);
                }
            }
        }
    }

    // ---- deterministic reduction ----
    #pragma unroll
    for (int off = 16; off > 0; off >>= 1) {
        accA0 += __shfl_xor_sync(0xffffffffu, accA0, off);
        accA1 += __shfl_xor_sync(0xffffffffu, accA1, off);
        accL2 += __shfl_xor_sync(0xffffffffu, accL2, off);
    }
    __syncthreads();
    if (l == 0) {
        if (rg == 1) { red[2 * cg] = accA0; red[2 * cg + 1] = accA1; }
        red[16 + w] = accL2;
    }
    __syncthreads();
    if (t < 16) out[bb + t] = red[t] + red[16 + t];
}

extern "C" void kernel_launch(void* const* d_in, const int* in_sizes, int n_in,
                              void* d_out, int out_size) {
    const float* x  = (const float*)d_in[0];
    const float* w0 = (const float*)d_in[1];
    const float* b0 = (const float*)d_in[2];
    const float* w1 = (const float*)d_in[3];
    const float* b1 = (const float*)d_in[4];
    const float* w2 = (const float*)d_in[5];
    const float* b2 = (const float*)d_in[6];
    const float* wl = (const float*)d_in[7];
    float* out = (float*)d_out;

    cudaFuncSetAttribute(cin_mma, cudaFuncAttributeMaxDynamicSharedMemorySize,
                         SM_TOTAL);

    int np = 40 * 8192;
    prep_w<<<(np + 255) / 256, 256>>>(w0, 40, 0);
    prep_w<<<(np + 255) / 256, 256>>>(w1, 64, 40);
    prep_w<<<(np + 255) / 256, 256>>>(w2, 64, 80);

    cin_mma<<<128, 512, SM_TOTAL>>>(x, b0, b1, b2, wl, out);
}

// round 15
// speedup vs baseline: 1.3832x; 1.0659x over previous
#include <cuda_runtime.h>
#include <cuda_fp16.h>
#include <cstdint>

// smem: A ring 8x16KB, pvS f32 [64][260] (stride-260 -> conflict-free), red
#define SM_A(s)   ((s) * 16384)
#define SM_PV     131072
#define PVS       260
#define SM_RED    197632
#define SM_TOTAL  197760

// W in m16n8k16 A-fragment order: [g=L*40+m][rb][ks][lane] x 8 halfs (16B)
__device__ __align__(16) __half g_wA[983040];

__device__ __forceinline__ uint32_t sh_addr(const void* p) {
    return (uint32_t)__cvta_generic_to_shared(p);
}

__device__ __forceinline__ void mma16816(float* c, const uint4& a,
                                         uint32_t bq0, uint32_t bq1) {
    asm volatile(
        "mma.sync.aligned.m16n8k16.row.col.f32.f16.f16.f32 "
        "{%0,%1,%2,%3}, {%4,%5,%6,%7}, {%8,%9}, {%0,%1,%2,%3};"
        : "+f"(c[0]), "+f"(c[1]), "+f"(c[2]), "+f"(c[3])
        : "r"(a.x), "r"(a.y), "r"(a.z), "r"(a.w), "r"(bq0), "r"(bq1));
}

#define CPA16(dst, src) \
    asm volatile("cp.async.cg.shared.global [%0], [%1], 16;" :: "r"(dst), "l"(src))

__device__ __forceinline__ uint32_t hmul2u(uint32_t a, uint32_t b) {
    __half2 r = __hmul2(*(__half2*)&a, *(__half2*)&b);
    return *(uint32_t*)&r;
}

// all 3 layers in one launch: w[o][k][m] f32 (k < H real) -> g_wA fragment order
__global__ void prep_w_all(const float* __restrict__ w0,
                           const float* __restrict__ w1,
                           const float* __restrict__ w2) {
    int idx = blockIdx.x * blockDim.x + threadIdx.x;
    if (idx >= 3 * 40 * 8192) return;
    int Lw = idx / (40 * 8192);
    int rI = idx - Lw * (40 * 8192);
    const float* w = (Lw == 0) ? w0 : ((Lw == 1) ? w1 : w2);
    int H = (Lw == 0) ? 40 : 64;
    int e    = rI & 7;
    int lane = (rI >> 3) & 31;
    int ks   = (rI >> 8) & 3;
    int rb   = (rI >> 10) & 7;
    int m    = rI >> 13;
    int r = rb * 16 + (lane >> 2) + ((e >> 1) & 1) * 8;
    int k = ks * 16 + (lane & 3) * 2 + (e & 1) + ((e >> 2) & 1) * 8;
    float v = (k < H) ? w[r * (H * 40) + k * 40 + m] : 0.f;
    g_wA[(size_t)(Lw * 40 + m) * 8192 + (rI & 8191)] = __float2half(v);
}

__global__ void __launch_bounds__(512, 1) cin_mma(
    const float* __restrict__ x,
    const float* __restrict__ b0, const float* __restrict__ b1,
    const float* __restrict__ b2,
    const float* __restrict__ wl, float* __restrict__ out)
{
    extern __shared__ char smp[];
    float* pvS = (float*)(smp + SM_PV);
    float* red = (float*)(smp + SM_RED);
    int t = threadIdx.x, w = t >> 5, l = t & 31;
    int bb = blockIdx.x * 16;
    int rg = w >> 3, cg = w & 7;
    int lq = l >> 2, lr = l & 3;

    // x column pointers for this lane's fragment columns
    const float* xpA[4];    // layers 0/1: cols cg*32 + nt*8 + lq
    const float* xp2[2];    // layer 2:    cols w*16  + nt*8 + lq
    #pragma unroll
    for (int nt = 0; nt < 4; nt++) {
        int n = cg * 32 + nt * 8 + lq;
        xpA[nt] = x + (size_t)(bb + (n >> 4)) * 640 + (n & 15);
    }
    #pragma unroll
    for (int nt = 0; nt < 2; nt++) {
        int n = w * 16 + nt * 8 + lq;
        xp2[nt] = x + (size_t)(bb + (n >> 4)) * 640 + (n & 15);
    }

    // prev fragments in registers: pf[ks][nt][d] = half2{prev[k,n], prev[k+1,n]},
    // k = ks*16 + lr*2 + d*8.  Layer 0: prev = x (h<40 real).
    uint32_t pf[4][4][2];
    #pragma unroll
    for (int ks = 0; ks < 4; ks++)
        #pragma unroll
        for (int nt = 0; nt < 4; nt++)
            #pragma unroll
            for (int d = 0; d < 2; d++) {
                int h = ks * 16 + lr * 2 + d * 8;
                float v0 = (h < 40) ? __ldg(xpA[nt] + h * 16) : 0.f;
                float v1 = (h + 1 < 40) ? __ldg(xpA[nt] + (h + 1) * 16) : 0.f;
                __half2 hv = __floats2half2_rn(v0, v1);
                pf[ks][nt][d] = *(uint32_t*)&hv;
            }

    float C[4][4][4];
    float accA0 = 0.f, accA1 = 0.f, accL2 = 0.f;
    const float* biasArr[3] = { b0, b1, b2 };

    for (int L = 0; L < 3; L++) {
        bool isL0 = (L == 0), isL2 = (L == 2);
        int ksN = isL0 ? 3 : 4;     // L0: k>=48 rows are exact zeros
        #pragma unroll
        for (int rbi = 0; rbi < 4; rbi++)
            #pragma unroll
            for (int nt = 0; nt < 4; nt++)
                #pragma unroll
                for (int i = 0; i < 4; i++) C[rbi][nt][i] = 0.f;
        int g0 = L * 40;

        {   // prologue: prefetch chunks 0..3 -> slots 0..3 (one group)
            #pragma unroll
            for (int ch = 0; ch < 4; ch++) {
                const char* s = (const char*)g_wA + (size_t)(g0 + ch) * 16384;
                uint32_t d = sh_addr(smp + SM_A(ch)) + (uint32_t)(t * 16);
                if (!isL2) CPA16(d, s + t * 16);
                CPA16(d + 8192, s + 8192 + t * 16);   // L2 reads only upper half
            }
            asm volatile("cp.async.commit_group;" ::: "memory");
        }

        // x for chunk 0 (prefetched ahead each chunk thereafter)
        float xn[4];
        if (!isL2) {
            #pragma unroll
            for (int nt = 0; nt < 4; nt++) xn[nt] = __ldg(xpA[nt]);
        } else {
            #pragma unroll
            for (int nt = 0; nt < 2; nt++) xn[nt] = __ldg(xp2[nt]);
        }

        for (int cq = 0; cq < 10; cq++) {
            int c0 = cq * 4;
            asm volatile("cp.async.wait_group 0;" ::: "memory");  // quad cq landed
            __syncthreads();                                       // ring reuse safe
            if (c0 + 4 < 40) {  // prefetch quad cq+1 -> slots (c0+4+i)&7
                #pragma unroll
                for (int ch = 0; ch < 4; ch++) {
                    const char* s = (const char*)g_wA +
                                    (size_t)(g0 + c0 + 4 + ch) * 16384;
                    uint32_t d = sh_addr(smp + SM_A((c0 + 4 + ch) & 7)) +
                                 (uint32_t)(t * 16);
                    if (!isL2) CPA16(d, s + t * 16);
                    CPA16(d + 8192, s + 8192 + t * 16);
                }
            }
            asm volatile("cp.async.commit_group;" ::: "memory");

            #pragma unroll
            for (int sub = 0; sub < 4; sub++) {
                int c = c0 + sub;
                const char* Ab = smp + SM_A(c & 7);

                if (!isL2) {
                    uint32_t xh[4];
                    #pragma unroll
                    for (int nt = 0; nt < 4; nt++) {
                        __half2 h2 = __float2half2_rn(xn[nt]);
                        xh[nt] = *(uint32_t*)&h2;
                    }
                    if (c + 1 < 40) {
                        #pragma unroll
                        for (int nt = 0; nt < 4; nt++)
                            xn[nt] = __ldg(xpA[nt] + (c + 1) * 16);
                    }
                    #pragma unroll
                    for (int ks = 0; ks < 4; ks++) {
                        if (ks >= ksN) break;
                        uint32_t b[4][2];
                        #pragma unroll
                        for (int nt = 0; nt < 4; nt++) {
                            b[nt][0] = hmul2u(pf[ks][nt][0], xh[nt]);
                            b[nt][1] = hmul2u(pf[ks][nt][1], xh[nt]);
                        }
                        #pragma unroll
                        for (int rbi = 0; rbi < 4; rbi++) {
                            uint4 a = *(const uint4*)(Ab +
                                (((rg * 4 + rbi) * 4 + ks) * 32 + l) * 16);
                            #pragma unroll
                            for (int nt = 0; nt < 4; nt++)
                                mma16816(C[rbi][nt], a, b[nt][0], b[nt][1]);
                        }
                    }
                } else {        // L2: rows 64..127, warp w covers cols w*16..+16
                    uint32_t xh[2];
                    #pragma unroll
                    for (int nt = 0; nt < 2; nt++) {
                        __half2 h2 = __float2half2_rn(xn[nt]);
                        xh[nt] = *(uint32_t*)&h2;
                    }
                    if (c + 1 < 40) {
                        #pragma unroll
                        for (int nt = 0; nt < 2; nt++)
                            xn[nt] = __ldg(xp2[nt] + (c + 1) * 16);
                    }
                    #pragma unroll
                    for (int ks = 0; ks < 4; ks++) {
                        uint32_t b[2][2];
                        #pragma unroll
                        for (int nt = 0; nt < 2; nt++) {
                            b[nt][0] = hmul2u(pf[ks][nt][0], xh[nt]);
                            b[nt][1] = hmul2u(pf[ks][nt][1], xh[nt]);
                        }
                        #pragma unroll
                        for (int rbi = 0; rbi < 4; rbi++) {
                            uint4 a = *(const uint4*)(Ab +
                                (((4 + rbi) * 4 + ks) * 32 + l) * 16);
                            #pragma unroll
                            for (int nt = 0; nt < 2; nt++)
                                mma16816(C[rbi][nt], a, b[nt][0], b[nt][1]);
                        }
                    }
                }
            }
        }

        // ---- epilogue ----
        const float* bp = biasArr[L];
        if (!isL2) {
            #pragma unroll
            for (int rbi = 0; rbi < 4; rbi++) {
                int r0 = (rg * 4 + rbi) * 16 + lq;
                float bv0 = __ldg(bp + r0), bv1 = __ldg(bp + r0 + 8);
                float wl0 = 0.f, wl1 = 0.f;
                if (rg == 1) {
                    wl0 = __ldg(wl + L * 64 + r0 - 64);
                    wl1 = __ldg(wl + L * 64 + r0 - 56);
                }
                #pragma unroll
                for (int nt = 0; nt < 4; nt++) {
                    int n0 = cg * 32 + nt * 8 + lr * 2;
                    float v0 = fmaxf(C[rbi][nt][0] + bv0, 0.f);
                    float v1 = fmaxf(C[rbi][nt][1] + bv0, 0.f);
                    float v2 = fmaxf(C[rbi][nt][2] + bv1, 0.f);
                    float v3 = fmaxf(C[rbi][nt][3] + bv1, 0.f);
                    if (rg == 0) {              // prev half -> pvS (stride 260)
                        pvS[r0 * PVS + n0]           = v0;
                        pvS[r0 * PVS + n0 + 1]       = v1;
                        pvS[(r0 + 8) * PVS + n0]     = v2;
                        pvS[(r0 + 8) * PVS + n0 + 1] = v3;
                    } else {                    // direct half -> weighted acc
                        float a = wl0 * (v0 + v1) + wl1 * (v2 + v3);
                        if (nt < 2) accA0 += a; else accA1 += a;
                    }
                }
            }
            __syncthreads();                    // pvS complete
            // reload prev fragments for layer L+1
            if (L == 0) {                       // next layer uses cols cg*32+...
                #pragma unroll
                for (int ks = 0; ks < 4; ks++)
                    #pragma unroll
                    for (int nt = 0; nt < 4; nt++)
                        #pragma unroll
                        for (int d = 0; d < 2; d++) {
                            int h = ks * 16 + lr * 2 + d * 8;
                            int n = cg * 32 + nt * 8 + lq;
                            __half2 hv = __floats2half2_rn(pvS[h * PVS + n],
                                                           pvS[(h + 1) * PVS + n]);
                            pf[ks][nt][d] = *(uint32_t*)&hv;
                        }
            } else {                            // next layer is L2: cols w*16+...
                #pragma unroll
                for (int ks = 0; ks < 4; ks++)
                    #pragma unroll
                    for (int nt = 0; nt < 2; nt++)
                        #pragma unroll
                        for (int d = 0; d < 2; d++) {
                            int h = ks * 16 + lr * 2 + d * 8;
                            int n = w * 16 + nt * 8 + lq;
                            __half2 hv = __floats2half2_rn(pvS[h * PVS + n],
                                                           pvS[(h + 1) * PVS + n]);
                            pf[ks][nt][d] = *(uint32_t*)&hv;
                        }
            }
        } else {
            #pragma unroll
            for (int rbi = 0; rbi < 4; rbi++) {
                int r0 = (4 + rbi) * 16 + lq;
                float bv0 = __ldg(bp + r0), bv1 = __ldg(bp + r0 + 8);
                float wl0 = __ldg(wl + 128 + r0 - 64);
                float wl1 = __ldg(wl + 128 + r0 - 56);
                #pragma unroll
                for (int nt = 0; nt < 2; nt++) {
                    float v0 = fmaxf(C[rbi][nt][0] + bv0, 0.f);
                    float v1 = fmaxf(C[rbi][nt][1] + bv0, 0.f);
                    float v2 = fmaxf(C[rbi][nt][2] + bv1, 0.f);
                    float v3 = fmaxf(C[rbi][nt][3] + bv1, 0.f);
                    accL2 += wl0 * (v0 + v1) + wl1 * (v2 + v3);
                }
            }
        }
    }

    // ---- deterministic reduction ----
    #pragma unroll
    for (int off = 16; off > 0; off >>= 1) {
        accA0 += __shfl_xor_sync(0xffffffffu, accA0, off);
        accA1 += __shfl_xor_sync(0xffffffffu, accA1, off);
        accL2 += __shfl_xor_sync(0xffffffffu, accL2, off);
    }
    __syncthreads();
    if (l == 0) {
        if (rg == 1) { red[2 * cg] = accA0; red[2 * cg + 1] = accA1; }
        red[16 + w] = accL2;
    }
    __syncthreads();
    if (t < 16) out[bb + t] = red[t] + red[16 + t];
}

extern "C" void kernel_launch(void* const* d_in, const int* in_sizes, int n_in,
                              void* d_out, int out_size) {
    const float* x  = (const float*)d_in[0];
    const float* w0 = (const float*)d_in[1];
    const float* b0 = (const float*)d_in[2];
    const float* w1 = (const float*)d_in[3];
    const float* b1 = (const float*)d_in[4];
    const float* w2 = (const float*)d_in[5];
    const float* b2 = (const float*)d_in[6];
    const float* wl = (const float*)d_in[7];
    float* out = (float*)d_out;

    cudaFuncSetAttribute(cin_mma, cudaFuncAttributeMaxDynamicSharedMemorySize,
                         SM_TOTAL);

    int np = 3 * 40 * 8192;
    prep_w_all<<<(np + 255) / 256, 256>>>(w0, w1, w2);

    cin_mma<<<128, 512, SM_TOTAL>>>(x, b0, b1, b2, wl, out);
}